// round 14
// baseline (speedup 1.0000x reference)
#include <cuda_runtime.h>

// ---------------- problem constants ----------------
#define NROWS     2048
#define RROWS     4          // 4 rows per CTA, split into 2 independent groups of 2 rows
#define NTHREADS  512
#define SPONGE_N  1024
#define HALFW     512
#define QUARTW    256
#define ACT_N     256
#define DEPTH_N   8
#define BDEPTH_N  10
#define BF_SIZE   3072
#define BF_HALF   1536
#define BF_QUART  768
#define BF_DEPTH  12

// per-group (2-row) layout
#define SP2       2320                   // sponge buffer stride (floats), >= i2(1023)+2, 16B mult
#define M2OFF     (2*SP2)                // 4640
#define BF2       6928                   // BF buffer stride, >= ib2(3071)+2, 16B mult
#define GSTRIDE   (2*BF2)                // 13856 floats per group
#define SMEM_FLOATS (2*GSTRIDE)          // 27712 floats = 110848 B -> 2 CTAs/SM

// fixed address offsets (verified constant over valid ranges)
#define SR1 288      // i2(A+128)-i2(A)
#define SR2 576      // +256
#define SR3 864      // +384
#define SW2 1168     // i2(2m+512)-i2(2m)
#define BR1 864      // ib2(A+384)-ib2(A)
#define BR2 1728     // +768
#define BR3 2592     // +1152
#define BW2 3472     // ib2(2u+1536)-ib2(2u)

// ---------------- precomputed tables ----------------
__device__ __align__(16) float2 g_rot  [DEPTH_N*BDEPTH_N*HALFW];  // sponge (cos,sin)
__device__ __align__(16) float2 g_bfrot[BF_DEPTH*BF_HALF];        // final butterfly
__device__ float4 g_act  [DEPTH_N*ACT_N];           // (bias, c, t, 1/c)
__device__ int    g_recall[DEPTH_N*ACT_N];
__device__ int    g_outidx[2048];

__global__ void prep_kernel(const float* __restrict__ angles,
                            const float* __restrict__ bf_angles,
                            const float* __restrict__ act_bias,
                            const float* __restrict__ act_curv,
                            const void*  __restrict__ recall_raw,
                            const void*  __restrict__ out_raw)
{
    int i = blockIdx.x * blockDim.x + threadIdx.x;
    const int NROT = DEPTH_N*BDEPTH_N*HALFW;       // 40960
    const int NBF  = BF_DEPTH*BF_HALF;             // 18432
    if (i < NROT) {
        float s, c; __sincosf(__ldg(angles + i), &s, &c);
        g_rot[i] = make_float2(c, s);
    } else if (i < NROT + NBF) {
        int j = i - NROT;
        float s, c; __sincosf(__ldg(bf_angles + j), &s, &c);
        g_bfrot[j] = make_float2(c, s);
    } else if (i < NROT + NBF + DEPTH_N*ACT_N) {
        int k = i - NROT - NBF;
        float cu = __ldg(act_curv + k);
        float c  = 0.5f*(cu + sqrtf(cu*cu + 1.0f));
        g_act[k] = make_float4(__ldg(act_bias + k), c,
                               0.25f*3.14159265358979323846f/c, 1.0f/c);
    }
    // dtype-robust index decode (int32 vs int64)
    if (i < 2048) {
        const int* o32 = (const int*)out_raw;
        bool is64 = (o32[1]==0 && o32[3]==0 && o32[5]==0 && o32[7]==0);
        if (is64) {
            g_outidx[i] = (int)((const long long*)out_raw)[i];
            g_recall[i] = (int)((const long long*)recall_raw)[i];
        } else {
            g_outidx[i] = o32[i];
            g_recall[i] = ((const int*)recall_raw)[i];
        }
    }
}

// ---------------- 2-row padded indexing (rows at +0,+1) ----------------
__device__ __forceinline__ int i2s(int p) { return 2*p + ((p>>4)<<2) + ((p>>9)<<4); }
__device__ __forceinline__ int ib2(int p) { return 2*p + ((p>>4)<<2) + ((p>=1536)?16:0); }
__device__ __forceinline__ int mb2(int p) { return 2*p + ((p>>4)<<2); }

__device__ __forceinline__ float actf(float x, float c, float tt, float invc) {
    const float OOS2 = 0.70710678118654752f;
    float r = invc*(OOS2 - __cosf(0.78539816339744831f + c*x));
    if (x >  tt) r = invc*OOS2 + (x - tt);
    if (x < -tt) r = invc*(OOS2 - 1.0f);
    return r;
}

__device__ __forceinline__ float2 mix2(float c, float s, float2 a, float2 b) {
    return make_float2(c*a.x + s*b.x, c*a.y + s*b.y);
}

// coefficient prefetch for sponge stage s5 (unit m)
__device__ __forceinline__ void pf_sp(const float2* __restrict__ rotd, int s5, int m,
                                      float2& c1, float2& c2, float4& c4)
{
    const float2* r0 = rotd + (2*s5)*HALFW;
    c1 = __ldg(r0 + m);
    c2 = __ldg(r0 + m + QUARTW);
    c4 = __ldg((const float4*)(rotd + (2*s5+1)*HALFW) + m);
}

__global__ void __launch_bounds__(NTHREADS, 2)
sponge_kernel(const float* __restrict__ X,
              const float* __restrict__ scales,
              float* __restrict__ out)
{
    extern __shared__ float sb[];
    const int t    = threadIdx.x;
    const int g    = t >> 8;            // row-pair group 0/1
    const int i    = t & 255;           // unit index within group
    const int row0 = blockIdx.x * RROWS;
    const int r0   = row0 + 2*g;        // this group's rows: r0, r0+1
    float* const SG   = sb + g*GSTRIDE;
    float* const MEM2 = SG + M2OFF;
    const int barid = 1 + g;

#define GBAR() asm volatile("bar.sync %0, 256;" :: "r"(barid) : "memory")

    // ---- load X * scales into sponge buffer 0 (group-private) ----
    #pragma unroll
    for (int k = 0; k < 4; k++) {
        int p = i + 256*k;
        float sc = scales[p];
        float v0 = X[(size_t)r0     * SPONGE_N + p] * sc;
        float v1 = X[(size_t)(r0+1) * SPONGE_N + p] * sc;
        *(float2*)(SG + i2s(p)) = make_float2(v0, v1);
    }

    // ---- per-thread constants: unit m = i ----
    const int A1 = (i >> 1) + (i & 1) * HALFW;
    const int rb = i2s(A1);
    const int wb = i2s(2*i);

    // prime the coefficient pipeline: depth 0, stage 0
    float2 c1, c2; float4 c4;
    pf_sp(g_rot, 0, i, c1, c2, c4);
    float4 ap;  int mi = 0;

    GBAR();

    int cur = 0;
    for (int d = 0; d < DEPTH_N; d++) {
        const float2* rotd = g_rot + d*(BDEPTH_N*HALFW);
        // ---- 5 fused double-layer stages with prefetched coefficients ----
        #pragma unroll
        for (int s5 = 0; s5 < BDEPTH_N/2; s5++) {
            float2 u1 = c1, u2 = c2; float4 u4 = c4;
            if (s5 < BDEPTH_N/2 - 1) {
                pf_sp(rotd, s5+1, i, c1, c2, c4);
            } else {
                ap = g_act[d*ACT_N + i];
                mi = __ldg(g_recall + d*ACT_N + i);
            }
            const float* IN  = SG + cur*SP2;
            float*       OUT = SG + (cur^1)*SP2;

            float2 a1 = *(const float2*)(IN + rb);
            float2 a2 = *(const float2*)(IN + rb + SR1);
            float2 b1 = *(const float2*)(IN + rb + SR2);
            float2 b2 = *(const float2*)(IN + rb + SR3);
            float2 y1e = mix2(u1.x,  u1.y, a1, b1);
            float2 y1o = mix2(u1.x, -u1.y, b1, a1);
            float2 y2e = mix2(u2.x,  u2.y, a2, b2);
            float2 y2o = mix2(u2.x, -u2.y, b2, a2);
            float2 z0 = mix2(u4.x,  u4.y, y1e, y2e);   // pos 2m
            float2 z1 = mix2(u4.z,  u4.w, y1o, y2o);   // pos 2m+1
            float2 z2 = mix2(u4.x, -u4.y, y2e, y1e);   // pos 2m+512
            float2 z3 = mix2(u4.z, -u4.w, y2o, y1o);   // pos 2m+513
            *(float4*)(OUT + wb)       = make_float4(z0.x, z0.y, z1.x, z1.y);
            *(float4*)(OUT + wb + SW2) = make_float4(z2.x, z2.y, z3.x, z3.y);
            cur ^= 1;
            GBAR();
        }

        // ---- activation / mem store / recall: ONE barrier ----
        {
            const float* S  = SG + cur*SP2;
            float*       OB = SG + (cur^1)*SP2;
            if (d < DEPTH_N-1) pf_sp(rotd + BDEPTH_N*HALFW, 0, i, c1, c2, c4);

            float2 x = *(const float2*)(S + i2s(HALFW + i));
            float2 o0, o1;                          // positions 2i (+), 2i+1 (-)
            o0.x = actf( (x.x + ap.x), ap.y, ap.z, ap.w);
            o0.y = actf( (x.y + ap.x), ap.y, ap.z, ap.w);
            o1.x = actf(-(x.x + ap.x), ap.y, ap.z, ap.w);
            o1.y = actf(-(x.y + ap.x), ap.y, ap.z, ap.w);
            *(float4*)(OB + i2s(2*i)) = make_float4(o0.x, o0.y, o1.x, o1.y);

            float2 mv1 = *(const float2*)(S + i2s(i));
            float2 mv2 = *(const float2*)(S + i2s(i + 256));
            *(float2*)(MEM2 + mb2(d*HALFW + i))       = mv1;
            *(float2*)(MEM2 + mb2(d*HALFW + i + 256)) = mv2;

            float2 kv = *(const float2*)(S + i2s(3*QUARTW + i));
            *(float2*)(OB + i2s(HALFW + i)) = kv;

            float2 rv = (mi >= d*HALFW)
                ? *(const float2*)(S + i2s(mi - d*HALFW))
                : *(const float2*)(MEM2 + mb2(mi));
            *(float2*)(OB + i2s(3*QUARTW + i)) = rv;

            cur ^= 1;
            GBAR();
        }
    }
    // 6 flips per depth x 8 -> cur = 0; sponge in buffer 0

    // ---- build pre = [mem[out_idx] (2048), sponge (1024)] in BF buffer 0 ----
    {
        float2 sv[4];
        #pragma unroll
        for (int k = 0; k < 4; k++)
            sv[k] = *(const float2*)(SG + i2s(i + 256*k));
        GBAR();                                      // sponge reads done before clobber
        #pragma unroll
        for (int k = 0; k < 8; k++) {
            int pp = i + 256*k;
            int oi = g_outidx[pp];
            *(float2*)(SG + ib2(pp)) = *(const float2*)(MEM2 + mb2(oi));
        }
        GBAR();                                      // mem reads done before tail clobbers
        #pragma unroll
        for (int k = 0; k < 4; k++)
            *(float2*)(SG + ib2(2048 + i + 256*k)) = sv[k];
        GBAR();
    }

    // ---- final 12-layer butterfly as 6 fused double-layers, 3 units/thread ----
    int rbB[3], wbB[3];
    #pragma unroll
    for (int j2 = 0; j2 < 3; j2++) {
        int u  = i + 256*j2;
        int Ab = (u >> 1) + (u & 1)*BF_HALF;
        rbB[j2] = ib2(Ab);
        wbB[j2] = ib2(2*u);
    }

    int bcur = 0;
    for (int s6 = 0; s6 < BF_DEPTH/2; s6++) {
        const float2* r0c = g_bfrot + (2*s6)*BF_HALF;
        const float4* r1c = (const float4*)(g_bfrot + (2*s6+1)*BF_HALF);
        float2 C1[3], C2[3]; float4 C4[3];
        #pragma unroll
        for (int j2 = 0; j2 < 3; j2++) {
            int u = i + 256*j2;
            C1[j2] = __ldg(r0c + u);
            C2[j2] = __ldg(r0c + u + BF_QUART);
            C4[j2] = __ldg(r1c + u);
        }
        const float* IN  = SG + bcur*BF2;
        float*       OUT = SG + (bcur^1)*BF2;
        #pragma unroll
        for (int j2 = 0; j2 < 3; j2++) {
            int rbs = rbB[j2], wbs = wbB[j2];
            float2 a1 = *(const float2*)(IN + rbs);
            float2 a2 = *(const float2*)(IN + rbs + BR1);
            float2 b1 = *(const float2*)(IN + rbs + BR2);
            float2 b2 = *(const float2*)(IN + rbs + BR3);
            float2 y1e = mix2(C1[j2].x,  C1[j2].y, a1, b1);
            float2 y1o = mix2(C1[j2].x, -C1[j2].y, b1, a1);
            float2 y2e = mix2(C2[j2].x,  C2[j2].y, a2, b2);
            float2 y2o = mix2(C2[j2].x, -C2[j2].y, b2, a2);
            float2 z0 = mix2(C4[j2].x,  C4[j2].y, y1e, y2e);
            float2 z1 = mix2(C4[j2].z,  C4[j2].w, y1o, y2o);
            float2 z2 = mix2(C4[j2].x, -C4[j2].y, y2e, y1e);
            float2 z3 = mix2(C4[j2].z, -C4[j2].w, y2o, y1o);
            *(float4*)(OUT + wbs)       = make_float4(z0.x, z0.y, z1.x, z1.y);
            *(float4*)(OUT + wbs + BW2) = make_float4(z2.x, z2.y, z3.x, z3.y);
        }
        bcur ^= 1;
        GBAR();
    }

    // result in buffer 0 (6 flips); emit first 512 columns, this group's 2 rows
    #pragma unroll
    for (int k = 0; k < 2; k++) {
        int p = i + 256*k;
        float2 v = *(const float2*)(SG + ib2(p));
        out[(size_t)r0     * HALFW + p] = v.x;
        out[(size_t)(r0+1) * HALFW + p] = v.y;
    }
#undef GBAR
}

extern "C" void kernel_launch(void* const* d_in, const int* in_sizes, int n_in,
                              void* d_out, int out_size)
{
    (void)in_sizes; (void)n_in; (void)out_size;
    const float* X          = (const float*)d_in[0];
    const float* scales     = (const float*)d_in[1];
    const float* angles     = (const float*)d_in[2];
    const float* act_bias   = (const float*)d_in[3];
    // d_in[4] = act_activation (unused by reference)
    const float* act_curv   = (const float*)d_in[5];
    const float* bf_angles  = (const float*)d_in[6];
    // d_in[7] = shuffle_perm (deterministic riffle, computed inline)
    const void*  recall_raw = d_in[8];
    const void*  out_raw    = d_in[9];
    // d_in[10] = bf_perm (deterministic riffle, computed inline)
    float* out = (float*)d_out;

    const int totalPrep = DEPTH_N*BDEPTH_N*HALFW + BF_DEPTH*BF_HALF + DEPTH_N*ACT_N;
    prep_kernel<<<(totalPrep + 511)/512, 512>>>(angles, bf_angles, act_bias, act_curv,
                                                recall_raw, out_raw);

    size_t smem = SMEM_FLOATS * sizeof(float);   // 110848 B
    cudaFuncSetAttribute(sponge_kernel, cudaFuncAttributeMaxDynamicSharedMemorySize, (int)smem);
    sponge_kernel<<<NROWS/RROWS, NTHREADS, smem>>>(X, scales, out);
}

// round 15
// speedup vs baseline: 1.0659x; 1.0659x over previous
#include <cuda_runtime.h>

// ---------------- problem constants ----------------
#define NROWS     2048
#define RROWS     4          // batch rows per CTA (split 2+2 across thread row-halves)
#define NTHREADS  512
#define SPONGE_N  1024
#define HALFW     512
#define QUARTW    256
#define ACT_N     256
#define DEPTH_N   8
#define BDEPTH_N  10
#define BF_SIZE   3072
#define BF_HALF   1536
#define BF_QUART  768
#define BF_DEPTH  12

#define SP_STRIDE   4624                 // >= isp(1023)+4, 16B aligned
#define MEM_OFF     (2*SP_STRIDE)        // 9248
#define BF_STRIDE   13840                // >= ibf(3071)+4
#define SMEM_FLOATS (2*BF_STRIDE)        // 27680 floats = 110720 B -> 2 CTAs/SM

// ---------------- precomputed tables ----------------
__device__ __align__(16) float2 g_rot  [DEPTH_N*BDEPTH_N*HALFW];  // sponge (cos,sin)
__device__ __align__(16) float2 g_bfrot[BF_DEPTH*BF_HALF];        // final butterfly
__device__ float4 g_act  [DEPTH_N*ACT_N];           // (bias, c, t, 1/c)
__device__ int    g_recall[DEPTH_N*ACT_N];
__device__ int    g_outidx[2048];

__global__ void prep_kernel(const float* __restrict__ angles,
                            const float* __restrict__ bf_angles,
                            const float* __restrict__ act_bias,
                            const float* __restrict__ act_curv,
                            const void*  __restrict__ recall_raw,
                            const void*  __restrict__ out_raw)
{
    int i = blockIdx.x * blockDim.x + threadIdx.x;
    const int NROT = DEPTH_N*BDEPTH_N*HALFW;       // 40960
    const int NBF  = BF_DEPTH*BF_HALF;             // 18432
    if (i < NROT) {
        float s, c; __sincosf(__ldg(angles + i), &s, &c);
        g_rot[i] = make_float2(c, s);
    } else if (i < NROT + NBF) {
        int j = i - NROT;
        float s, c; __sincosf(__ldg(bf_angles + j), &s, &c);
        g_bfrot[j] = make_float2(c, s);
    } else if (i < NROT + NBF + DEPTH_N*ACT_N) {
        int k = i - NROT - NBF;
        float cu = __ldg(act_curv + k);
        float c  = 0.5f*(cu + sqrtf(cu*cu + 1.0f));
        g_act[k] = make_float4(__ldg(act_bias + k), c,
                               0.25f*3.14159265358979323846f/c, 1.0f/c);
    }
    // dtype-robust index decode (int32 vs int64)
    if (i < 2048) {
        const int* o32 = (const int*)out_raw;
        bool is64 = (o32[1]==0 && o32[3]==0 && o32[5]==0 && o32[7]==0);
        if (is64) {
            g_outidx[i] = (int)((const long long*)out_raw)[i];
            g_recall[i] = (int)((const long long*)recall_raw)[i];
        } else {
            g_outidx[i] = o32[i];
            g_recall[i] = ((const int*)recall_raw)[i];
        }
    }
}

// ---------------- padded shared-memory indexing ----------------
__device__ __forceinline__ int isp(int p) { return 4*p + ((p>>3)<<2) + ((p>>9)<<4); }
__device__ __forceinline__ int ibf(int p) { return 4*p + ((p>>3)<<2) + ((p>=1536)?16:0); }

// fixed offsets (verified constant across valid base positions)
#define SR1 576
#define SR2 1152
#define SR3 1728
#define SW1 4
#define SW2 2320
#define SW3 2324
#define BSTEP 864     // ibf(p+192)-ibf(p), within half
#define BWHI  6928    // ibf(p+1536)-ibf(p)

__device__ __forceinline__ float actf(float x, float c, float tt, float invc) {
    const float OOS2 = 0.70710678118654752f;
    float r = invc*(OOS2 - __cosf(0.78539816339744831f + c*x));
    if (x >  tt) r = invc*OOS2 + (x - tt);
    if (x < -tt) r = invc*(OOS2 - 1.0f);
    return r;
}

__device__ __forceinline__ float2 mix2(float c, float s, float2 a, float2 b) {
    return make_float2(c*a.x + s*b.x, c*a.y + s*b.y);
}

// in-place Givens rotation on a float2 pair (2 rows)
__device__ __forceinline__ void grot(float2& p, float2& r, float c, float s) {
    float2 pn = mix2(c,  s, p, r);
    float2 rn = mix2(c, -s, r, p);
    p = pn; r = rn;
}

// coefficient prefetch for sponge stage s5 of depth block rotd
__device__ __forceinline__ void pf_sp(const float2* __restrict__ rotd, int s5, int m,
                                      float2& c1, float2& c2, float4& c4)
{
    const float2* r0 = rotd + (2*s5)*HALFW;
    c1 = __ldg(r0 + m);
    c2 = __ldg(r0 + m + QUARTW);
    c4 = __ldg((const float4*)(rotd + (2*s5+1)*HALFW) + m);
}

__global__ void __launch_bounds__(NTHREADS, 2)
sponge_kernel(const float* __restrict__ X,
              const float* __restrict__ scales,
              float* __restrict__ out)
{
    extern __shared__ float sb[];
    const int t    = threadIdx.x;
    const int row0 = blockIdx.x * RROWS;
    float* const MEMB = sb + MEM_OFF;

    // ---- load X * scales into sponge buffer 0 ----
    {
        float sc0 = scales[t], sc1 = scales[t + HALFW];
        int i0 = isp(t), i1 = i0 + SW2;
        #pragma unroll
        for (int r = 0; r < RROWS; r++) {
            const float* xr = X + (size_t)(row0 + r) * SPONGE_N;
            sb[i0 + r] = xr[t]         * sc0;
            sb[i1 + r] = xr[t + HALFW] * sc1;
        }
    }

    // ---- per-thread constants: thread = (pair m, row-half rh) ----
    const int  m   = t >> 1;
    const int  rh  = t & 1;
    const bool odd = rh;
    const int  A1  = (m >> 1) + (m & 1) * HALFW;
    const int  rb  = isp(A1)  + 2*rh;
    const int  wb  = isp(2*m) + 2*rh;
    const int  w0  = isp(t);
    const int  w1  = w0 + SW2;
    const int  ja  = t >> 1;
    const int  qa  = (t >= QUARTW) ? (t - QUARTW) : 0;   // recall slot (valid t>=256)

    // prime the coefficient pipeline: depth 0, stage 0
    float2 c1, c2; float4 c4;
    pf_sp(g_rot, 0, m, c1, c2, c4);
    float4 ap;  int mi = 0;

    __syncthreads();

    int cur = 0;
    for (int d = 0; d < DEPTH_N; d++) {
        const float2* rotd = g_rot + d*(BDEPTH_N*HALFW);
        // ---- 5 fused double-layer stages with prefetched coefficients ----
        #pragma unroll
        for (int s5 = 0; s5 < BDEPTH_N/2; s5++) {
            float2 u1 = c1, u2 = c2; float4 u4 = c4;
            if (s5 < BDEPTH_N/2 - 1) {
                pf_sp(rotd, s5+1, m, c1, c2, c4);
            } else {
                ap = g_act[d*ACT_N + ja];
                mi = __ldg(g_recall + d*ACT_N + qa);
            }
            const float* IN  = sb + cur*SP_STRIDE;
            float*       OUT = sb + (cur^1)*SP_STRIDE;

            float2 a1 = *(const float2*)(IN + rb);
            float2 a2 = *(const float2*)(IN + rb + SR1);
            float2 b1 = *(const float2*)(IN + rb + SR2);
            float2 b2 = *(const float2*)(IN + rb + SR3);
            float2 y1e = mix2(u1.x,  u1.y, a1, b1);
            float2 y1o = mix2(u1.x, -u1.y, b1, a1);
            float2 y2e = mix2(u2.x,  u2.y, a2, b2);
            float2 y2o = mix2(u2.x, -u2.y, b2, a2);
            *(float2*)(OUT + wb)       = mix2(u4.x,  u4.y, y1e, y2e);
            *(float2*)(OUT + wb + SW1) = mix2(u4.z,  u4.w, y1o, y2o);
            *(float2*)(OUT + wb + SW2) = mix2(u4.x, -u4.y, y2e, y1e);
            *(float2*)(OUT + wb + SW3) = mix2(u4.z, -u4.w, y2o, y1o);
            cur ^= 1;
            __syncthreads();
        }

        // ---- activation / mem store / recall: ONE barrier (R9-proven) ----
        {
            const float* S    = sb + cur*SP_STRIDE;
            float*       OUTB = sb + (cur^1)*SP_STRIDE;
            if (d < DEPTH_N-1) pf_sp(rotd + BDEPTH_N*HALFW, 0, m, c1, c2, c4);

            float4 x  = *(const float4*)(S + isp(HALFW + ja));
            float sg  = odd ? -1.0f : 1.0f;
            float4 o;
            o.x = actf(sg*(x.x + ap.x), ap.y, ap.z, ap.w);
            o.y = actf(sg*(x.y + ap.x), ap.y, ap.z, ap.w);
            o.z = actf(sg*(x.z + ap.x), ap.y, ap.z, ap.w);
            o.w = actf(sg*(x.w + ap.x), ap.y, ap.z, ap.w);

            float4 mv = *(const float4*)(S + w0);
            *(float4*)(MEMB + (d*HALFW + t)*RROWS) = mv;

            *(float4*)(OUTB + w0) = o;                        // act_out -> [0,512)
            if (t < QUARTW) {
                float4 kv = *(const float4*)(S + isp(3*QUARTW + t));
                *(float4*)(OUTB + isp(HALFW + t)) = kv;       // [768,1024)->[512,768)
            } else {
                float4 rv = (mi >= d*HALFW)
                    ? *(const float4*)(S + isp(mi - d*HALFW))
                    : *(const float4*)(MEMB + mi*RROWS);
                *(float4*)(OUTB + isp(3*QUARTW + qa)) = rv;   // recall -> [768,1024)
            }
            cur ^= 1;
            __syncthreads();
        }
    }
    // 6 flips per depth x 8 -> cur = 0; sponge in buffer 0

    // ---- build pre = [mem[out_idx] (2048), sponge (1024)] in BF buffer 0 ----
    {
        float4 s0 = *(const float4*)(sb + w0);
        float4 s1 = *(const float4*)(sb + w1);
        int oi0 = g_outidx[t];
        int oi1 = g_outidx[t + NTHREADS];
        int oi2 = g_outidx[t + 2*NTHREADS];
        int oi3 = g_outidx[t + 3*NTHREADS];
        __syncthreads();
        *(float4*)(sb + ibf(t))              = *(const float4*)(MEMB + oi0*RROWS);
        *(float4*)(sb + ibf(t + NTHREADS))   = *(const float4*)(MEMB + oi1*RROWS);
        *(float4*)(sb + ibf(t + 2*NTHREADS)) = *(const float4*)(MEMB + oi2*RROWS);
        *(float4*)(sb + ibf(t + 3*NTHREADS)) = *(const float4*)(MEMB + oi3*RROWS);
        __syncthreads();
        *(float4*)(sb + ibf(2048 + t))         = s0;
        *(float4*)(sb + ibf(2048 + HALFW + t)) = s1;
        __syncthreads();
    }

    // ---- final 12-layer butterfly: 4 fused-3 stages (R8-verified closure) ----
    // unit u in [0,384): reads {A + 192w, w=0..7}, A = (u>>1) + (u&1)*1536;
    // 3-level in-register butterfly; writes {4u+q, 4u+q+1536}.
    // pass 0: u = m (units 0..255); pass 1: u = m+256 (threads t<256 only).
    {
        int bcur = 0;
        for (int st = 0; st < 4; st++) {
            const float2* a0 = g_bfrot + (3*st+0)*BF_HALF;
            const float2* a1 = g_bfrot + (3*st+1)*BF_HALF;
            const float2* a2 = g_bfrot + (3*st+2)*BF_HALF;
            const float* IN  = sb + bcur*BF_STRIDE;
            float*       OUT = sb + (bcur^1)*BF_STRIDE;
            #pragma unroll
            for (int ps = 0; ps < 2; ps++) {
                if (ps == 0 || t < 256) {
                    int u = m + 256*ps;
                    // coalesced coefficient loads from the raw (cos,sin) tables
                    float2 cA0 = __ldg(a0 + u);
                    float2 cA1 = __ldg(a0 + u + 384);
                    float2 cA2 = __ldg(a0 + u + 768);
                    float2 cA3 = __ldg(a0 + u + 1152);
                    float4 cC  = __ldg((const float4*)a1 + u);          // angles 2u,2u+1
                    float4 cD  = __ldg((const float4*)(a1 + 768) + u);  // 2u+768,2u+769
                    float4 cE  = __ldg((const float4*)a2 + 2*u);        // 4u,4u+1
                    float4 cF  = __ldg((const float4*)a2 + 2*u + 1);    // 4u+2,4u+3

                    int h   = u >> 1, e = u & 1;
                    int rbs = ibf(h) + BWHI*e + 2*rh;
                    int wbs = ibf(4*u) + 2*rh;

                    float2 v0 = *(const float2*)(IN + rbs + 0*BSTEP);
                    float2 v1 = *(const float2*)(IN + rbs + 1*BSTEP);
                    float2 v2 = *(const float2*)(IN + rbs + 2*BSTEP);
                    float2 v3 = *(const float2*)(IN + rbs + 3*BSTEP);
                    float2 v4 = *(const float2*)(IN + rbs + 4*BSTEP);
                    float2 v5 = *(const float2*)(IN + rbs + 5*BSTEP);
                    float2 v6 = *(const float2*)(IN + rbs + 6*BSTEP);
                    float2 v7 = *(const float2*)(IN + rbs + 7*BSTEP);

                    // L1: pairs (v_w, v_{w+4}), angles u + 384b
                    grot(v0, v4, cA0.x, cA0.y);
                    grot(v1, v5, cA1.x, cA1.y);
                    grot(v2, v6, cA2.x, cA2.y);
                    grot(v3, v7, cA3.x, cA3.y);
                    // L2: (v0,v2)=2u, (v4,v6)=2u+1, (v1,v3)=2u+768, (v5,v7)=2u+769
                    grot(v0, v2, cC.x, cC.y);
                    grot(v4, v6, cC.z, cC.w);
                    grot(v1, v3, cD.x, cD.y);
                    grot(v5, v7, cD.z, cD.w);
                    // L3: (v0,v1)=4u, (v2,v3)=4u+1, (v4,v5)=4u+2, (v6,v7)=4u+3
                    grot(v0, v1, cE.x, cE.y);
                    grot(v2, v3, cE.z, cE.w);
                    grot(v4, v5, cF.x, cF.y);
                    grot(v6, v7, cF.z, cF.w);

                    *(float2*)(OUT + wbs +  0)        = v0;
                    *(float2*)(OUT + wbs +  0 + BWHI) = v1;
                    *(float2*)(OUT + wbs +  4)        = v2;
                    *(float2*)(OUT + wbs +  4 + BWHI) = v3;
                    *(float2*)(OUT + wbs +  8)        = v4;
                    *(float2*)(OUT + wbs +  8 + BWHI) = v5;
                    *(float2*)(OUT + wbs + 12)        = v6;
                    *(float2*)(OUT + wbs + 12 + BWHI) = v7;
                }
            }
            bcur ^= 1;
            __syncthreads();
        }
    }

    // result in buffer 0 (4 flips); emit first 512 columns
    {
        float4 v = *(const float4*)(sb + ibf(t));
        out[(size_t)(row0 + 0)*HALFW + t] = v.x;
        out[(size_t)(row0 + 1)*HALFW + t] = v.y;
        out[(size_t)(row0 + 2)*HALFW + t] = v.z;
        out[(size_t)(row0 + 3)*HALFW + t] = v.w;
    }
}

extern "C" void kernel_launch(void* const* d_in, const int* in_sizes, int n_in,
                              void* d_out, int out_size)
{
    (void)in_sizes; (void)n_in; (void)out_size;
    const float* X          = (const float*)d_in[0];
    const float* scales     = (const float*)d_in[1];
    const float* angles     = (const float*)d_in[2];
    const float* act_bias   = (const float*)d_in[3];
    // d_in[4] = act_activation (unused by reference)
    const float* act_curv   = (const float*)d_in[5];
    const float* bf_angles  = (const float*)d_in[6];
    // d_in[7] = shuffle_perm (deterministic riffle, computed inline)
    const void*  recall_raw = d_in[8];
    const void*  out_raw    = d_in[9];
    // d_in[10] = bf_perm (deterministic riffle, computed inline)
    float* out = (float*)d_out;

    const int totalPrep = DEPTH_N*BDEPTH_N*HALFW + BF_DEPTH*BF_HALF + DEPTH_N*ACT_N;
    prep_kernel<<<(totalPrep + 511)/512, 512>>>(angles, bf_angles, act_bias, act_curv,
                                                recall_raw, out_raw);

    size_t smem = SMEM_FLOATS * sizeof(float);
    cudaFuncSetAttribute(sponge_kernel, cudaFuncAttributeMaxDynamicSharedMemorySize, (int)smem);
    sponge_kernel<<<NROWS/RROWS, NTHREADS, smem>>>(X, scales, out);
}

// round 16
// speedup vs baseline: 1.0821x; 1.0152x over previous
#include <cuda_runtime.h>

// ---------------- problem constants ----------------
#define NROWS     2048
#define RROWS     4          // batch rows per CTA (split 2+2 across thread row-halves)
#define NTHREADS  512
#define SPONGE_N  1024
#define HALFW     512
#define QUARTW    256
#define ACT_N     256
#define DEPTH_N   8
#define BDEPTH_N  10
#define BF_SIZE   3072
#define BF_HALF   1536
#define BF_QUART  768
#define BF_DEPTH  12

#define SP_STRIDE   4624                 // >= isp(1023)+4, 16B aligned
#define MEM_OFF     (2*SP_STRIDE)        // 9248
#define BF_STRIDE   13840                // >= ibf(3071)+4
#define SMEM_FLOATS (2*BF_STRIDE)        // 27680 floats = 110720 B -> 2 CTAs/SM

// ---------------- precomputed tables ----------------
__device__ __align__(16) float2 g_rot  [DEPTH_N*BDEPTH_N*HALFW];  // sponge (cos,sin)
__device__ __align__(16) float2 g_bfrot[BF_DEPTH*BF_HALF];        // final butterfly
__device__ float4 g_act  [DEPTH_N*ACT_N];           // (bias, c, t, 1/c)
__device__ int    g_recall[DEPTH_N*ACT_N];
__device__ int    g_outidx[2048];

__global__ void prep_kernel(const float* __restrict__ angles,
                            const float* __restrict__ bf_angles,
                            const float* __restrict__ act_bias,
                            const float* __restrict__ act_curv,
                            const void*  __restrict__ recall_raw,
                            const void*  __restrict__ out_raw)
{
    int i = blockIdx.x * blockDim.x + threadIdx.x;
    const int NROT = DEPTH_N*BDEPTH_N*HALFW;       // 40960
    const int NBF  = BF_DEPTH*BF_HALF;             // 18432
    if (i < NROT) {
        float s, c; __sincosf(__ldg(angles + i), &s, &c);
        g_rot[i] = make_float2(c, s);
    } else if (i < NROT + NBF) {
        int j = i - NROT;
        float s, c; __sincosf(__ldg(bf_angles + j), &s, &c);
        g_bfrot[j] = make_float2(c, s);
    } else if (i < NROT + NBF + DEPTH_N*ACT_N) {
        int k = i - NROT - NBF;
        float cu = __ldg(act_curv + k);
        float c  = 0.5f*(cu + sqrtf(cu*cu + 1.0f));
        g_act[k] = make_float4(__ldg(act_bias + k), c,
                               0.25f*3.14159265358979323846f/c, 1.0f/c);
    }
    // dtype-robust index decode (int32 vs int64)
    if (i < 2048) {
        const int* o32 = (const int*)out_raw;
        bool is64 = (o32[1]==0 && o32[3]==0 && o32[5]==0 && o32[7]==0);
        if (is64) {
            g_outidx[i] = (int)((const long long*)out_raw)[i];
            g_recall[i] = (int)((const long long*)recall_raw)[i];
        } else {
            g_outidx[i] = o32[i];
            g_recall[i] = ((const int*)recall_raw)[i];
        }
    }
}

// ---------------- padded shared-memory indexing ----------------
__device__ __forceinline__ int isp(int p) { return 4*p + ((p>>3)<<2) + ((p>>9)<<4); }
__device__ __forceinline__ int ibf(int p) { return 4*p + ((p>>3)<<2) + ((p>=1536)?16:0); }

// fixed offsets (verified constant across valid base positions)
#define SR1 576
#define SR2 1152
#define SR3 1728
#define SW1 4
#define SW2 2320       // isp(p+512)-isp(p)
#define SW3 2324
#define SSTEP 288      // isp(p+64)-isp(p), within half
#define BSTEP 864      // ibf(p+192)-ibf(p), within half
#define BWHI  6928     // ibf(p+1536)-ibf(p)

__device__ __forceinline__ float actf(float x, float c, float tt, float invc) {
    const float OOS2 = 0.70710678118654752f;
    float r = invc*(OOS2 - __cosf(0.78539816339744831f + c*x));
    if (x >  tt) r = invc*OOS2 + (x - tt);
    if (x < -tt) r = invc*(OOS2 - 1.0f);
    return r;
}

__device__ __forceinline__ float2 mix2(float c, float s, float2 a, float2 b) {
    return make_float2(c*a.x + s*b.x, c*a.y + s*b.y);
}

// in-place Givens rotation on a float2 pair (2 rows)
__device__ __forceinline__ void grot(float2& p, float2& r, float c, float s) {
    float2 pn = mix2(c,  s, p, r);
    float2 rn = mix2(c, -s, r, p);
    p = pn; r = rn;
}

// coefficient prefetch for sponge fused-2 stage s5 of depth block rotd
__device__ __forceinline__ void pf_sp(const float2* __restrict__ rotd, int s5, int m,
                                      float2& c1, float2& c2, float4& c4)
{
    const float2* r0 = rotd + (2*s5)*HALFW;
    c1 = __ldg(r0 + m);
    c2 = __ldg(r0 + m + QUARTW);
    c4 = __ldg((const float4*)(rotd + (2*s5+1)*HALFW) + m);
}

// generic 3-layer fused butterfly (R8-verified closure), float2 rows
// reads IN[rbs + step*w], w=0..7; writes OUT[wbs + {0,4,8,12}] (+whi)
__device__ __forceinline__ void fused3(const float* __restrict__ IN,
                                       float* __restrict__ OUT,
                                       int rbs, int step, int wbs, int whi,
                                       const float2* a0, const float2* a1,
                                       const float2* a2, int g, int quart)
{
    float2 cA0 = __ldg(a0 + g);
    float2 cA1 = __ldg(a0 + g + quart);
    float2 cA2 = __ldg(a0 + g + 2*quart);
    float2 cA3 = __ldg(a0 + g + 3*quart);
    float4 cC  = __ldg((const float4*)a1 + g);              // angles 2g, 2g+1
    float4 cD  = __ldg((const float4*)(a1 + 2*quart) + g);  // 2g+2q, 2g+2q+1
    float4 cE  = __ldg((const float4*)a2 + 2*g);            // 4g, 4g+1
    float4 cF  = __ldg((const float4*)a2 + 2*g + 1);        // 4g+2, 4g+3

    float2 v0 = *(const float2*)(IN + rbs + 0*step);
    float2 v1 = *(const float2*)(IN + rbs + 1*step);
    float2 v2 = *(const float2*)(IN + rbs + 2*step);
    float2 v3 = *(const float2*)(IN + rbs + 3*step);
    float2 v4 = *(const float2*)(IN + rbs + 4*step);
    float2 v5 = *(const float2*)(IN + rbs + 5*step);
    float2 v6 = *(const float2*)(IN + rbs + 6*step);
    float2 v7 = *(const float2*)(IN + rbs + 7*step);

    grot(v0, v4, cA0.x, cA0.y);
    grot(v1, v5, cA1.x, cA1.y);
    grot(v2, v6, cA2.x, cA2.y);
    grot(v3, v7, cA3.x, cA3.y);

    grot(v0, v2, cC.x, cC.y);
    grot(v4, v6, cC.z, cC.w);
    grot(v1, v3, cD.x, cD.y);
    grot(v5, v7, cD.z, cD.w);

    grot(v0, v1, cE.x, cE.y);
    grot(v2, v3, cE.z, cE.w);
    grot(v4, v5, cF.x, cF.y);
    grot(v6, v7, cF.z, cF.w);

    *(float2*)(OUT + wbs +  0)       = v0;
    *(float2*)(OUT + wbs +  0 + whi) = v1;
    *(float2*)(OUT + wbs +  4)       = v2;
    *(float2*)(OUT + wbs +  4 + whi) = v3;
    *(float2*)(OUT + wbs +  8)       = v4;
    *(float2*)(OUT + wbs +  8 + whi) = v5;
    *(float2*)(OUT + wbs + 12)       = v6;
    *(float2*)(OUT + wbs + 12 + whi) = v7;
}

__global__ void __launch_bounds__(NTHREADS, 2)
sponge_kernel(const float* __restrict__ X,
              const float* __restrict__ scales,
              float* __restrict__ out)
{
    extern __shared__ float sb[];
    const int t    = threadIdx.x;
    const int row0 = blockIdx.x * RROWS;
    float* const MEMB = sb + MEM_OFF;

    // ---- load X * scales into sponge buffer 0 ----
    {
        float sc0 = scales[t], sc1 = scales[t + HALFW];
        int i0 = isp(t), i1 = i0 + SW2;
        #pragma unroll
        for (int r = 0; r < RROWS; r++) {
            const float* xr = X + (size_t)(row0 + r) * SPONGE_N;
            sb[i0 + r] = xr[t]         * sc0;
            sb[i1 + r] = xr[t + HALFW] * sc1;
        }
    }

    // ---- per-thread constants: thread = (pair m, row-half rh) ----
    const int  m   = t >> 1;
    const int  rh  = t & 1;
    const bool odd = rh;
    const int  A1  = (m >> 1) + (m & 1) * HALFW;
    const int  rb  = isp(A1)  + 2*rh;
    const int  wb  = isp(2*m) + 2*rh;
    const int  w0  = isp(t);
    const int  w1  = w0 + SW2;
    const int  ja  = t >> 1;
    const int  qa  = (t >= QUARTW) ? (t - QUARTW) : 0;   // recall slot (valid t>=256)

    // sponge fused-3 constants (active t<256): unit gs = t>>1, same rh
    const int gs    = m;                         // valid for t<256 (gs in [0,128))
    const int rbs3  = isp(gs >> 1) + SW2*(gs & 1) + 2*rh;
    const int wbs3  = isp(4*gs) + 2*rh;

    float2 c1, c2; float4 c4;                    // fused-2 coeff pipeline
    float4 ap;  int mi = 0;

    __syncthreads();

    int cur = 0;
    for (int d = 0; d < DEPTH_N; d++) {
        const float2* rotd = g_rot + d*(BDEPTH_N*HALFW);

        // ---- two fused-3 stages (layers 0-2, 3-5); active threads t<256 ----
        #pragma unroll
        for (int st = 0; st < 2; st++) {
            if (st == 1) pf_sp(rotd, 3, m, c1, c2, c4);   // prefetch f2-A (layers 6,7)
            if (t < 256) {
                const float2* a0 = rotd + (3*st)*HALFW;
                fused3(sb + cur*SP_STRIDE, sb + (cur^1)*SP_STRIDE,
                       rbs3, SSTEP, wbs3, SW2,
                       a0, a0 + HALFW, a0 + 2*HALFW, gs, 128);
            }
            cur ^= 1;
            __syncthreads();
        }

        // ---- two fused-2 stages (layers 6-7, 8-9) with prefetch pipeline ----
        #pragma unroll
        for (int r2 = 0; r2 < 2; r2++) {
            float2 u1 = c1, u2 = c2; float4 u4 = c4;
            if (r2 == 0) {
                pf_sp(rotd, 4, m, c1, c2, c4);            // prefetch f2-B (layers 8,9)
            } else {
                ap = g_act[d*ACT_N + ja];
                mi = __ldg(g_recall + d*ACT_N + qa);
            }
            const float* IN  = sb + cur*SP_STRIDE;
            float*       OUT = sb + (cur^1)*SP_STRIDE;

            float2 a1 = *(const float2*)(IN + rb);
            float2 a2 = *(const float2*)(IN + rb + SR1);
            float2 b1 = *(const float2*)(IN + rb + SR2);
            float2 b2 = *(const float2*)(IN + rb + SR3);
            float2 y1e = mix2(u1.x,  u1.y, a1, b1);
            float2 y1o = mix2(u1.x, -u1.y, b1, a1);
            float2 y2e = mix2(u2.x,  u2.y, a2, b2);
            float2 y2o = mix2(u2.x, -u2.y, b2, a2);
            *(float2*)(OUT + wb)       = mix2(u4.x,  u4.y, y1e, y2e);
            *(float2*)(OUT + wb + SW1) = mix2(u4.z,  u4.w, y1o, y2o);
            *(float2*)(OUT + wb + SW2) = mix2(u4.x, -u4.y, y2e, y1e);
            *(float2*)(OUT + wb + SW3) = mix2(u4.z, -u4.w, y2o, y1o);
            cur ^= 1;
            __syncthreads();
        }

        // ---- activation / mem store / recall: ONE barrier (R9-proven) ----
        {
            const float* S    = sb + cur*SP_STRIDE;
            float*       OUTB = sb + (cur^1)*SP_STRIDE;

            float4 x  = *(const float4*)(S + isp(HALFW + ja));
            float sg  = odd ? -1.0f : 1.0f;
            float4 o;
            o.x = actf(sg*(x.x + ap.x), ap.y, ap.z, ap.w);
            o.y = actf(sg*(x.y + ap.x), ap.y, ap.z, ap.w);
            o.z = actf(sg*(x.z + ap.x), ap.y, ap.z, ap.w);
            o.w = actf(sg*(x.w + ap.x), ap.y, ap.z, ap.w);

            float4 mv = *(const float4*)(S + w0);
            *(float4*)(MEMB + (d*HALFW + t)*RROWS) = mv;

            *(float4*)(OUTB + w0) = o;                        // act_out -> [0,512)
            if (t < QUARTW) {
                float4 kv = *(const float4*)(S + isp(3*QUARTW + t));
                *(float4*)(OUTB + isp(HALFW + t)) = kv;       // [768,1024)->[512,768)
            } else {
                float4 rv = (mi >= d*HALFW)
                    ? *(const float4*)(S + isp(mi - d*HALFW))
                    : *(const float4*)(MEMB + mi*RROWS);
                *(float4*)(OUTB + isp(3*QUARTW + qa)) = rv;   // recall -> [768,1024)
            }
            cur ^= 1;
            __syncthreads();
        }
    }
    // 5 flips per depth x 8 = 40 -> cur = 0; sponge in buffer 0

    // ---- build pre = [mem[out_idx] (2048), sponge (1024)] in BF buffer 0 ----
    {
        float4 s0 = *(const float4*)(sb + w0);
        float4 s1 = *(const float4*)(sb + w1);
        int oi0 = g_outidx[t];
        int oi1 = g_outidx[t + NTHREADS];
        int oi2 = g_outidx[t + 2*NTHREADS];
        int oi3 = g_outidx[t + 3*NTHREADS];
        __syncthreads();
        *(float4*)(sb + ibf(t))              = *(const float4*)(MEMB + oi0*RROWS);
        *(float4*)(sb + ibf(t + NTHREADS))   = *(const float4*)(MEMB + oi1*RROWS);
        *(float4*)(sb + ibf(t + 2*NTHREADS)) = *(const float4*)(MEMB + oi2*RROWS);
        *(float4*)(sb + ibf(t + 3*NTHREADS)) = *(const float4*)(MEMB + oi3*RROWS);
        __syncthreads();
        *(float4*)(sb + ibf(2048 + t))         = s0;
        *(float4*)(sb + ibf(2048 + HALFW + t)) = s1;
        __syncthreads();
    }

    // ---- final 12-layer butterfly: 4 fused-3 stages (R15-proven) ----
    {
        int bcur = 0;
        for (int st = 0; st < 4; st++) {
            const float2* a0 = g_bfrot + (3*st+0)*BF_HALF;
            const float2* a1 = g_bfrot + (3*st+1)*BF_HALF;
            const float2* a2 = g_bfrot + (3*st+2)*BF_HALF;
            const float* IN  = sb + bcur*BF_STRIDE;
            float*       OUT = sb + (bcur^1)*BF_STRIDE;
            #pragma unroll
            for (int ps = 0; ps < 2; ps++) {
                if (ps == 0 || t < 256) {
                    int u = m + 256*ps;
                    int h = u >> 1, e = u & 1;
                    fused3(IN, OUT,
                           ibf(h) + BWHI*e + 2*rh, BSTEP,
                           ibf(4*u) + 2*rh, BWHI,
                           a0, a1, a2, u, 384);
                }
            }
            bcur ^= 1;
            __syncthreads();
        }
    }

    // result in buffer 0 (4 flips); emit first 512 columns
    {
        float4 v = *(const float4*)(sb + ibf(t));
        out[(size_t)(row0 + 0)*HALFW + t] = v.x;
        out[(size_t)(row0 + 1)*HALFW + t] = v.y;
        out[(size_t)(row0 + 2)*HALFW + t] = v.z;
        out[(size_t)(row0 + 3)*HALFW + t] = v.w;
    }
}

extern "C" void kernel_launch(void* const* d_in, const int* in_sizes, int n_in,
                              void* d_out, int out_size)
{
    (void)in_sizes; (void)n_in; (void)out_size;
    const float* X          = (const float*)d_in[0];
    const float* scales     = (const float*)d_in[1];
    const float* angles     = (const float*)d_in[2];
    const float* act_bias   = (const float*)d_in[3];
    // d_in[4] = act_activation (unused by reference)
    const float* act_curv   = (const float*)d_in[5];
    const float* bf_angles  = (const float*)d_in[6];
    // d_in[7] = shuffle_perm (deterministic riffle, computed inline)
    const void*  recall_raw = d_in[8];
    const void*  out_raw    = d_in[9];
    // d_in[10] = bf_perm (deterministic riffle, computed inline)
    float* out = (float*)d_out;

    const int totalPrep = DEPTH_N*BDEPTH_N*HALFW + BF_DEPTH*BF_HALF + DEPTH_N*ACT_N;
    prep_kernel<<<(totalPrep + 511)/512, 512>>>(angles, bf_angles, act_bias, act_curv,
                                                recall_raw, out_raw);

    size_t smem = SMEM_FLOATS * sizeof(float);
    cudaFuncSetAttribute(sponge_kernel, cudaFuncAttributeMaxDynamicSharedMemorySize, (int)smem);
    sponge_kernel<<<NROWS/RROWS, NTHREADS, smem>>>(X, scales, out);
}